// round 9
// baseline (speedup 1.0000x reference)
#include <cuda_runtime.h>
#include <math.h>

// Problem constants
#define BB   256
#define TT   784
#define HH   512
#define NC   10

// 8 row-groups x 16 col-blocks = 128 CTAs, all co-resident (1 CTA/SM)
#define NBLK 128
#define NTHR 512
#define NG   8              // k-groups per CTA
#define KR   64             // k-range per group (NG*KR = HH)
#define LDH  516            // smem row stride in floats: mod 32 == 4 -> conflict-free patterns
#define SCR  20             // scratch stride (floats) per (group,thread)
#define SPIN_CAP 10000000u  // watchdog: real waits are <1e3 polls; cap turns hang into signal

typedef unsigned long long ull;

// Scratch (device globals; no allocation)
__device__ __align__(16) float g_h[2][BB * HH];
__device__ __align__(16) float g_xT[TT * BB];   // inputs[:, order] transposed: [t][b]
// Per-CTA flags, 128B apart; [cta*32+0] = rows 0-15 half (A), [cta*32+8] = rows 16-31 half (B).
__device__ unsigned g_flag[NBLK * 32];

__device__ __forceinline__ ull ffma2(ull a, ull b, ull c) {
    ull d;
    asm("fma.rn.f32x2 %0, %1, %2, %3;" : "=l"(d) : "l"(a), "l"(b), "l"(c));
    return d;
}
__device__ __forceinline__ float u2sum(ull v) {
    float lo, hi;
    asm("mov.b64 {%0, %1}, %2;" : "=f"(lo), "=f"(hi) : "l"(v));
    return lo + hi;
}
__device__ __forceinline__ void st_release(unsigned* p, unsigned v) {
    asm volatile("st.release.gpu.global.u32 [%0], %1;" :: "l"(p), "r"(v) : "memory");
}
__device__ __forceinline__ unsigned ld_acquire(const unsigned* p) {
    unsigned v;
    asm volatile("ld.acquire.gpu.global.u32 %0, [%1];" : "=r"(v) : "l"(p) : "memory");
    return v;
}
__device__ __forceinline__ void bar_named(int id, int cnt) {
    asm volatile("bar.sync %0, %1;" :: "r"(id), "r"(cnt) : "memory");
}
// Bounded acquire-spin: waits until *p - target >= 0 (wrap-safe) or watchdog cap.
__device__ __forceinline__ void spin_until(const unsigned* p, unsigned target) {
    unsigned v, n = 0;
    do { v = ld_acquire(p); } while ((int)(v - target) < 0 && ++n < SPIN_CAP);
}

extern "C" __global__ void __launch_bounds__(NTHR, 1)
rnn_persistent(const float* __restrict__ inputs,     // (B, T) f32
               const void* __restrict__ y_raw,       // (B,)   i32/i64 (detected)
               const void* __restrict__ order_raw,   // (T,)   i32/i64 (detected)
               const float* __restrict__ W_ih,       // (H,1)
               const float* __restrict__ b_ih,       // (H,)
               const float* __restrict__ W_hh,       // (H,H)
               const float* __restrict__ b_hh,       // (H,)
               const float* __restrict__ lin_W,      // (10,H)
               const float* __restrict__ lin_b,      // (10,)
               float* __restrict__ out, int out_size)
{
    extern __shared__ float smem[];
    float* w_sm    = smem;                         // [32][LDH]
    float* h_sm    = smem + 32 * LDH;              // [32][LDH]
    float* scratch = smem + 64 * LDH;              // [NG][64][SCR]
    float* s_wb    = scratch + NG * 64 * SCR;      // [0..31]=w_ih, [32..63]=bias per local col
    unsigned* s_u  = (unsigned*)(s_wb + 64);       // [0]=base

    const int tid = threadIdx.x;
    const int g   = tid >> 6;            // k-group 0..7, owns k in [KR*g, KR*g+KR)
    const int t64 = tid & 63;
    const int ty  = t64 >> 3;            // 0..7  -> rows {ty, ty+8, ty+16, ty+24}
    const int tx  = t64 & 7;             // 0..7  -> cols {tx, tx+8, tx+16, tx+24}

    const int rb    = blockIdx.x >> 4;   // row group 0..7
    const int cb    = blockIdx.x & 15;   // col block 0..15
    const int row0g = rb * 32;
    const int col0g = cb * 32;

    const bool is_i64 = (((const int*)order_raw)[1] == 0);   // arange detect

    if (tid == 0) s_u[0] = g_flag[blockIdx.x * 32];

    // ---- W_hh slice into smem, [c_local][k] stride LDH: ONCE ----
    {
        const int c  = tid >> 4;         // local col 0..31
        const int p0 = tid & 15;
        const float4* src = (const float4*)(W_hh + (size_t)(col0g + c) * HH);
        float* dst = w_sm + c * LDH;
        #pragma unroll
        for (int it = 0; it < 8; ++it) {
            int cc = p0 + (it << 4);
            *(float4*)(dst + 4 * cc) = src[cc];
        }
    }
    // Per-col params into smem
    if (tid < 32) {
        int c = col0g + tid;
        s_wb[tid]      = W_ih[c];
        s_wb[32 + tid] = b_ih[c] + b_hh[c];
    }
    // Zero h0 for our tile
    {
        int zr = tid >> 4, zc = (tid & 15) << 1;
        *(float2*)(g_h[0] + (size_t)(row0g + zr) * HH + col0g + zc) = make_float2(0.f, 0.f);
    }
    // ---- ONE-TIME x transpose: this CTA fills g_xT[t][row0g..+32] for its t-slice.
    {
        for (int idx = tid; idx < 49 * 32; idx += NTHR) {
            const int tt = 49 * cb + (idx >> 5);   // 784 = 16 * 49
            const int r  = idx & 31;
            const int o  = is_i64 ? (int)((const long long*)order_raw)[tt]
                                  : ((const int*)order_raw)[tt];
            g_xT[(size_t)tt * BB + row0g + r] = inputs[(size_t)(row0g + r) * TT + o];
        }
    }
    __syncthreads();
    const unsigned base = s_u[0];
    if (tid == 0) {                      // h0 + xT slice ready (both halves)
        st_release(&g_flag[blockIdx.x * 32 + 0], base + 1);
        st_release(&g_flag[blockIdx.x * 32 + 8], base + 1);
    }

    // Compute-phase pointers
    const float* hb[4];
    const float* wbp[4];
    #pragma unroll
    for (int i = 0; i < 4; ++i) hb[i]  = h_sm + (ty + 8 * i) * LDH + KR * g;
    #pragma unroll
    for (int j = 0; j < 4; ++j) wbp[j] = w_sm + (tx + 8 * j) * LDH + KR * g;

    // Fill mapping (per warp-half): warp w of group fills rows [16w, 16w+16) of the k-slice.
    const int fw    = t64 >> 5;          // 0 or 1: which row half this warp fills
    const int fl    = t64 & 31;          // lane
    const int fr0   = 16 * fw + (fl >> 4);   // + 2j, j=0..7
    const int fc4   = fl & 15;               // float4 chunk within 64-float slice
    const int half_off = 8 * fw;             // flag offset: 0 = A (rows 0-15), 8 = B

    // Reduce mapping (coalesced stores): warp rw owns rows {2rw, 2rw+1};
    const int rw    = tid >> 5;
    const int lane  = tid & 31;
    const int row_l = 2 * rw + (lane >> 4);
    const int m     = lane & 15;
    const int c0    = 2 * m, c1 = 2 * m + 1;
    const int own0  = ((row_l & 7) << 3) | (c0 & 7);
    const int own1  = own0 + 1;
    const int slot  = ((row_l >> 3) << 2) | (c0 >> 3);

    int p = 0;
    for (int t = 0; t < TT; ++t) {
        // ---- per-warp-half wait: all 16 row-group CTAs must have published
        //      THIS row half of buffer p ----
        if (fl < 16)
            spin_until(&g_flag[((rb << 4) + fl) * 32 + half_off], base + 1 + (unsigned)t);
        __syncwarp(0xffffffffu);

        // ---- fill my row-half of my 64-k slice (L1 bypass: lines are stale) ----
        #pragma unroll
        for (int j = 0; j < 8; ++j) {
            const int r = fr0 + 2 * j;
            float4 v = __ldcg((const float4*)(g_h[p] + (size_t)(row0g + r) * HH + KR * g) + fc4);
            *(float4*)(h_sm + r * LDH + KR * g + 4 * fc4) = v;
        }
        bar_named(1 + g, 64);            // join both halves of my group's slice

        // ---- 4x4 microtile over my 64-k range; f32x2-packed accumulators ----
        ull a00 = 0, a01 = 0, a02 = 0, a03 = 0;
        ull a10 = 0, a11 = 0, a12 = 0, a13 = 0;
        ull a20 = 0, a21 = 0, a22 = 0, a23 = 0;
        ull a30 = 0, a31 = 0, a32 = 0, a33 = 0;
        #pragma unroll 2
        for (int kk = 0; kk < KR; kk += 4) {
            ulonglong2 H0 = *(const ulonglong2*)(hb[0] + kk);
            ulonglong2 H1 = *(const ulonglong2*)(hb[1] + kk);
            ulonglong2 H2 = *(const ulonglong2*)(hb[2] + kk);
            ulonglong2 H3 = *(const ulonglong2*)(hb[3] + kk);
            ulonglong2 W0 = *(const ulonglong2*)(wbp[0] + kk);
            ulonglong2 W1 = *(const ulonglong2*)(wbp[1] + kk);
            ulonglong2 W2 = *(const ulonglong2*)(wbp[2] + kk);
            ulonglong2 W3 = *(const ulonglong2*)(wbp[3] + kk);
            a00 = ffma2(H0.x, W0.x, a00); a00 = ffma2(H0.y, W0.y, a00);
            a01 = ffma2(H0.x, W1.x, a01); a01 = ffma2(H0.y, W1.y, a01);
            a02 = ffma2(H0.x, W2.x, a02); a02 = ffma2(H0.y, W2.y, a02);
            a03 = ffma2(H0.x, W3.x, a03); a03 = ffma2(H0.y, W3.y, a03);
            a10 = ffma2(H1.x, W0.x, a10); a10 = ffma2(H1.y, W0.y, a10);
            a11 = ffma2(H1.x, W1.x, a11); a11 = ffma2(H1.y, W1.y, a11);
            a12 = ffma2(H1.x, W2.x, a12); a12 = ffma2(H1.y, W2.y, a12);
            a13 = ffma2(H1.x, W3.x, a13); a13 = ffma2(H1.y, W3.y, a13);
            a20 = ffma2(H2.x, W0.x, a20); a20 = ffma2(H2.y, W0.y, a20);
            a21 = ffma2(H2.x, W1.x, a21); a21 = ffma2(H2.y, W1.y, a21);
            a22 = ffma2(H2.x, W2.x, a22); a22 = ffma2(H2.y, W2.y, a22);
            a23 = ffma2(H2.x, W3.x, a23); a23 = ffma2(H2.y, W3.y, a23);
            a30 = ffma2(H3.x, W0.x, a30); a30 = ffma2(H3.y, W0.y, a30);
            a31 = ffma2(H3.x, W1.x, a31); a31 = ffma2(H3.y, W1.y, a31);
            a32 = ffma2(H3.x, W2.x, a32); a32 = ffma2(H3.y, W2.y, a32);
            a33 = ffma2(H3.x, W3.x, a33); a33 = ffma2(H3.y, W3.y, a33);
        }
        // publish partials: scratch[g][t64][0..15], stride SCR (conflict-free STS.128)
        {
            float* dst = scratch + (size_t)(g * 64 + t64) * SCR;
            *(float4*)(dst +  0) = make_float4(u2sum(a00), u2sum(a01), u2sum(a02), u2sum(a03));
            *(float4*)(dst +  4) = make_float4(u2sum(a10), u2sum(a11), u2sum(a12), u2sum(a13));
            *(float4*)(dst +  8) = make_float4(u2sum(a20), u2sum(a21), u2sum(a22), u2sum(a23));
            *(float4*)(dst + 12) = make_float4(u2sum(a30), u2sum(a31), u2sum(a32), u2sum(a33));
        }
        __syncthreads();   // k-reduction join: all partials visible (the ONE full bar)

        // ---- distributed reduce: contiguous float2 per thread -> coalesced STG.64.
        //      Warps 0-7 handle rows 0-15 (half A), warps 8-15 rows 16-31 (half B). ----
        {
            float acc0 = 0.f, acc1 = 0.f;
            #pragma unroll
            for (int gg = 0; gg < NG; ++gg) {
                const float* sc = scratch + (size_t)(gg * 64) * SCR;
                acc0 += sc[(size_t)own0 * SCR + slot];
                acc1 += sc[(size_t)own1 * SCR + slot];
            }
            const float xr = g_xT[(size_t)t * BB + row0g + row_l];
            float v0 = tanhf(fmaf(xr, s_wb[c0], s_wb[32 + c0]) + acc0);
            float v1 = tanhf(fmaf(xr, s_wb[c1], s_wb[32 + c1]) + acc1);
            *(float2*)(g_h[p ^ 1] + (size_t)(row0g + row_l) * HH + col0g + c0) =
                make_float2(v0, v1);
        }
        // Early split release: half A as soon as rows 0-15 are stored; B likewise.
        if (rw < 8) {
            bar_named(9, 256);
            if (tid == 0)   st_release(&g_flag[blockIdx.x * 32 + 0], base + 2 + (unsigned)t);
        } else {
            bar_named(10, 256);
            if (tid == 256) st_release(&g_flag[blockIdx.x * 32 + 8], base + 2 + (unsigned)t);
        }
        p ^= 1;
    }
    // final h in g_h[0] (784 steps, even)

    // ---- Epilogue on block 0: wait whole grid (both halves), then head + softmax ----
    if (blockIdx.x == 0) {
        if (tid < NBLK)
            spin_until(&g_flag[tid * 32 + 0], base + 1 + TT);
        else if (tid < 2 * NBLK)
            spin_until(&g_flag[(tid - NBLK) * 32 + 8], base + 1 + TT);
        __syncthreads();

        __shared__ float s_loss[BB];
        __shared__ int   s_corr[BB];
        if (tid < BB) {
            const int b = tid;
            const float* hrow = g_h[0] + (size_t)b * HH;

            float logit[NC];
            #pragma unroll
            for (int c = 0; c < NC; ++c) logit[c] = lin_b[c];
            for (int k = 0; k < HH; k += 4) {
                float4 hv = __ldcg((const float4*)(hrow + k));
                #pragma unroll
                for (int c = 0; c < NC; ++c) {
                    float4 wv = *(const float4*)(lin_W + (size_t)c * HH + k);
                    logit[c] = fmaf(hv.x, wv.x, logit[c]);
                    logit[c] = fmaf(hv.y, wv.y, logit[c]);
                    logit[c] = fmaf(hv.z, wv.z, logit[c]);
                    logit[c] = fmaf(hv.w, wv.w, logit[c]);
                }
            }
            float mx = logit[0]; int pred = 0;
            #pragma unroll
            for (int c = 1; c < NC; ++c)
                if (logit[c] > mx) { mx = logit[c]; pred = c; }
            float se = 0.f;
            #pragma unroll
            for (int c = 0; c < NC; ++c) se += expf(logit[c] - mx);
            const float lse = mx + logf(se);

            const int yb = is_i64 ? (int)((const long long*)y_raw)[b]
                                  : ((const int*)y_raw)[b];
            s_loss[b] = lse - logit[yb];
            s_corr[b] = (pred == yb) ? 1 : 0;
        }
        __syncthreads();
        if (tid == 0) {
            float L = 0.f; int C = 0;
            for (int i = 0; i < BB; ++i) { L += s_loss[i]; C += s_corr[i]; }
            out[0] = L / (float)BB;
            if (out_size >= 2) out[1] = (float)C;
        }
    }
}

extern "C" void kernel_launch(void* const* d_in, const int* in_sizes, int n_in,
                              void* d_out, int out_size) {
    // Identify inputs by element count (robust to ordering).
    const float *inputs = 0, *W_ih = 0, *b_ih = 0, *W_hh = 0, *b_hh = 0,
                *lin_W = 0, *lin_b = 0;
    const void *y = 0, *order = 0;
    int n512 = 0;
    for (int i = 0; i < n_in; ++i) {
        const int s = in_sizes[i];
        const void* ptr = d_in[i];
        if      (s == 200704) inputs = (const float*)ptr;
        else if (s == 262144) W_hh   = (const float*)ptr;
        else if (s == 5120)   lin_W  = (const float*)ptr;
        else if (s == 10)     lin_b  = (const float*)ptr;
        else if (s == 784)    order  = ptr;
        else if (s == 256)    y      = ptr;
        else if (s == 512) {
            if      (n512 == 0) W_ih = (const float*)ptr;
            else if (n512 == 1) b_ih = (const float*)ptr;
            else                b_hh = (const float*)ptr;
            ++n512;
        }
    }
    float* out = (float*)d_out;

    // smem: w[32][516] + h[32][516] + scratch[8][64][20] + wb[64] + u
    const size_t smem_bytes =
        ((size_t)64 * LDH + (size_t)NG * 64 * SCR + 64) * sizeof(float) + 64;
    cudaFuncSetAttribute(rnn_persistent,
                         cudaFuncAttributeMaxDynamicSharedMemorySize, (int)smem_bytes);
    rnn_persistent<<<NBLK, NTHR, smem_bytes>>>(inputs, y, order, W_ih, b_ih,
                                               W_hh, b_hh, lin_W, lin_b, out,
                                               out_size);
}

// round 10
// speedup vs baseline: 1.1459x; 1.1459x over previous
#include <cuda_runtime.h>
#include <math.h>

// Problem constants
#define BB   256
#define TT   784
#define HH   512
#define NC   10

// 8 row-groups x 16 col-blocks = 128 CTAs, all co-resident (1 CTA/SM)
#define NBLK 128
#define NTHR 512
#define NG   8              // k-groups per CTA
#define KR   64             // k-range per group (NG*KR = HH)
#define LDH  516            // smem row stride in floats: mod 32 == 4 -> conflict-free W loads
#define SCR  20             // scratch stride (floats) per (group,thread)
#define SPIN_CAP 10000000u  // watchdog: real waits are <1e3 polls; cap turns hang into signal

typedef unsigned long long ull;

// Scratch (device globals; no allocation)
__device__ __align__(16) float g_h[2][BB * HH];
__device__ __align__(16) float g_xT[TT * BB];   // inputs[:, order] transposed: [t][b]
__device__ unsigned g_flag[NBLK * 32];   // one flag per CTA, 128B apart; monotonic across replays

__device__ __forceinline__ ull ffma2(ull a, ull b, ull c) {
    ull d;
    asm("fma.rn.f32x2 %0, %1, %2, %3;" : "=l"(d) : "l"(a), "l"(b), "l"(c));
    return d;
}
__device__ __forceinline__ float u2sum(ull v) {
    float lo, hi;
    asm("mov.b64 {%0, %1}, %2;" : "=f"(lo), "=f"(hi) : "l"(v));
    return lo + hi;
}
// L2 (L1-bypass) 16B load, repacked as two f32x2 lanes. mov.b64 folds to register renames.
__device__ __forceinline__ ulonglong2 ldcg_u2(const float* p) {
    float4 v = __ldcg((const float4*)p);
    ulonglong2 r;
    asm("mov.b64 %0, {%2, %3};\n\tmov.b64 %1, {%4, %5};"
        : "=l"(r.x), "=l"(r.y) : "f"(v.x), "f"(v.y), "f"(v.z), "f"(v.w));
    return r;
}
__device__ __forceinline__ ulonglong2 lds_u2(const float* p) {
    ulonglong2 r = *(const ulonglong2*)p;
    return r;
}
__device__ __forceinline__ void st_release(unsigned* p, unsigned v) {
    asm volatile("st.release.gpu.global.u32 [%0], %1;" :: "l"(p), "r"(v) : "memory");
}
__device__ __forceinline__ unsigned ld_acquire(const unsigned* p) {
    unsigned v;
    asm volatile("ld.acquire.gpu.global.u32 %0, [%1];" : "=r"(v) : "l"(p) : "memory");
    return v;
}
__device__ __forceinline__ void bar_named(int id, int cnt) {
    asm volatile("bar.sync %0, %1;" :: "r"(id), "r"(cnt) : "memory");
}
// Bounded acquire-spin: waits until *p - target >= 0 (wrap-safe) or watchdog cap.
__device__ __forceinline__ void spin_until(const unsigned* p, unsigned target) {
    unsigned v, n = 0;
    do { v = ld_acquire(p); } while ((int)(v - target) < 0 && ++n < SPIN_CAP);
}

extern "C" __global__ void __launch_bounds__(NTHR, 1)
rnn_persistent(const float* __restrict__ inputs,     // (B, T) f32
               const void* __restrict__ y_raw,       // (B,)   i32/i64 (detected)
               const void* __restrict__ order_raw,   // (T,)   i32/i64 (detected)
               const float* __restrict__ W_ih,       // (H,1)
               const float* __restrict__ b_ih,       // (H,)
               const float* __restrict__ W_hh,       // (H,H)
               const float* __restrict__ b_hh,       // (H,)
               const float* __restrict__ lin_W,      // (10,H)
               const float* __restrict__ lin_b,      // (10,)
               float* __restrict__ out, int out_size)
{
    extern __shared__ float smem[];
    float* w_sm    = smem;                         // [32][LDH]
    float* scratch = smem + 32 * LDH;              // [NG][64][SCR]
    float* s_wb    = scratch + NG * 64 * SCR;      // [0..31]=w_ih, [32..63]=bias per local col
    unsigned* s_u  = (unsigned*)(s_wb + 64);       // [0]=base

    const int tid = threadIdx.x;
    const int g   = tid >> 6;            // k-group 0..7, owns k in [KR*g, KR*g+KR)
    const int t64 = tid & 63;
    const int ty  = t64 >> 3;            // 0..7  -> rows {ty, ty+8, ty+16, ty+24}
    const int tx  = t64 & 7;             // 0..7  -> cols {tx, tx+8, tx+16, tx+24}

    const int rb    = blockIdx.x >> 4;   // row group 0..7
    const int cb    = blockIdx.x & 15;   // col block 0..15
    const int row0g = rb * 32;
    const int col0g = cb * 32;

    const bool is_i64 = (((const int*)order_raw)[1] == 0);   // arange detect

    if (tid == 0) s_u[0] = g_flag[blockIdx.x * 32];

    // ---- W_hh slice into smem, [c_local][k] stride LDH: ONCE ----
    {
        const int c  = tid >> 4;         // local col 0..31
        const int p0 = tid & 15;
        const float4* src = (const float4*)(W_hh + (size_t)(col0g + c) * HH);
        float* dst = w_sm + c * LDH;
        #pragma unroll
        for (int it = 0; it < 8; ++it) {
            int cc = p0 + (it << 4);
            *(float4*)(dst + 4 * cc) = src[cc];
        }
    }
    // Per-col params into smem
    if (tid < 32) {
        int c = col0g + tid;
        s_wb[tid]      = W_ih[c];
        s_wb[32 + tid] = b_ih[c] + b_hh[c];
    }
    // Zero h0 for our tile
    {
        int zr = tid >> 4, zc = (tid & 15) << 1;
        *(float2*)(g_h[0] + (size_t)(row0g + zr) * HH + col0g + zc) = make_float2(0.f, 0.f);
    }
    // ---- ONE-TIME x transpose: this CTA fills g_xT[t][row0g..+32] for its t-slice. ----
    {
        for (int idx = tid; idx < 49 * 32; idx += NTHR) {
            const int tt = 49 * cb + (idx >> 5);   // 784 = 16 * 49
            const int r  = idx & 31;
            const int o  = is_i64 ? (int)((const long long*)order_raw)[tt]
                                  : ((const int*)order_raw)[tt];
            g_xT[(size_t)tt * BB + row0g + r] = inputs[(size_t)(row0g + r) * TT + o];
        }
    }
    __syncthreads();
    const unsigned base = s_u[0];
    if (tid == 0) st_release(&g_flag[blockIdx.x * 32], base + 1);   // h0 + xT slice ready

    // W smem pointers (loop-invariant)
    const float* wbp[4];
    #pragma unroll
    for (int j = 0; j < 4; ++j) wbp[j] = w_sm + (tx + 8 * j) * LDH + KR * g;

    // Reduce mapping (coalesced stores): warp rw owns rows {2rw, 2rw+1};
    const int rw    = tid >> 5;
    const int lane  = tid & 31;
    const int row_l = 2 * rw + (lane >> 4);
    const int m     = lane & 15;
    const int c0    = 2 * m, c1 = 2 * m + 1;
    const int own0  = ((row_l & 7) << 3) | (c0 & 7);
    const int own1  = own0 + 1;
    const int slot  = ((row_l >> 3) << 2) | (c0 >> 3);

    int p = 0;
    for (int t = 0; t < TT; ++t) {
        // ---- per-group wait: only my 2 producer CTAs (cols 64g..64g+64) ----
        if (t64 < 2)
            spin_until(&g_flag[((rb << 4) + 2 * g + t64) * 32], base + 1 + (unsigned)t);
        bar_named(1 + g, 64);

        // H row base pointers in GLOBAL (L2): no smem staging this round.
        const float* hg0 = g_h[p] + (size_t)(row0g + ty +  0) * HH + KR * g;
        const float* hg1 = g_h[p] + (size_t)(row0g + ty +  8) * HH + KR * g;
        const float* hg2 = g_h[p] + (size_t)(row0g + ty + 16) * HH + KR * g;
        const float* hg3 = g_h[p] + (size_t)(row0g + ty + 24) * HH + KR * g;

        // ---- 4x4 microtile over my 64-k range; H direct from L2, W from smem ----
        ull a00 = 0, a01 = 0, a02 = 0, a03 = 0;
        ull a10 = 0, a11 = 0, a12 = 0, a13 = 0;
        ull a20 = 0, a21 = 0, a22 = 0, a23 = 0;
        ull a30 = 0, a31 = 0, a32 = 0, a33 = 0;
        #pragma unroll 4
        for (int kk = 0; kk < KR; kk += 4) {
            ulonglong2 H0 = ldcg_u2(hg0 + kk);
            ulonglong2 H1 = ldcg_u2(hg1 + kk);
            ulonglong2 H2 = ldcg_u2(hg2 + kk);
            ulonglong2 H3 = ldcg_u2(hg3 + kk);
            ulonglong2 W0 = lds_u2(wbp[0] + kk);
            ulonglong2 W1 = lds_u2(wbp[1] + kk);
            ulonglong2 W2 = lds_u2(wbp[2] + kk);
            ulonglong2 W3 = lds_u2(wbp[3] + kk);
            a00 = ffma2(H0.x, W0.x, a00); a00 = ffma2(H0.y, W0.y, a00);
            a01 = ffma2(H0.x, W1.x, a01); a01 = ffma2(H0.y, W1.y, a01);
            a02 = ffma2(H0.x, W2.x, a02); a02 = ffma2(H0.y, W2.y, a02);
            a03 = ffma2(H0.x, W3.x, a03); a03 = ffma2(H0.y, W3.y, a03);
            a10 = ffma2(H1.x, W0.x, a10); a10 = ffma2(H1.y, W0.y, a10);
            a11 = ffma2(H1.x, W1.x, a11); a11 = ffma2(H1.y, W1.y, a11);
            a12 = ffma2(H1.x, W2.x, a12); a12 = ffma2(H1.y, W2.y, a12);
            a13 = ffma2(H1.x, W3.x, a13); a13 = ffma2(H1.y, W3.y, a13);
            a20 = ffma2(H2.x, W0.x, a20); a20 = ffma2(H2.y, W0.y, a20);
            a21 = ffma2(H2.x, W1.x, a21); a21 = ffma2(H2.y, W1.y, a21);
            a22 = ffma2(H2.x, W2.x, a22); a22 = ffma2(H2.y, W2.y, a22);
            a23 = ffma2(H2.x, W3.x, a23); a23 = ffma2(H2.y, W3.y, a23);
            a30 = ffma2(H3.x, W0.x, a30); a30 = ffma2(H3.y, W0.y, a30);
            a31 = ffma2(H3.x, W1.x, a31); a31 = ffma2(H3.y, W1.y, a31);
            a32 = ffma2(H3.x, W2.x, a32); a32 = ffma2(H3.y, W2.y, a32);
            a33 = ffma2(H3.x, W3.x, a33); a33 = ffma2(H3.y, W3.y, a33);
        }
        // publish partials: scratch[g][t64][0..15], stride SCR (conflict-free STS.128)
        {
            float* dst = scratch + (size_t)(g * 64 + t64) * SCR;
            *(float4*)(dst +  0) = make_float4(u2sum(a00), u2sum(a01), u2sum(a02), u2sum(a03));
            *(float4*)(dst +  4) = make_float4(u2sum(a10), u2sum(a11), u2sum(a12), u2sum(a13));
            *(float4*)(dst +  8) = make_float4(u2sum(a20), u2sum(a21), u2sum(a22), u2sum(a23));
            *(float4*)(dst + 12) = make_float4(u2sum(a30), u2sum(a31), u2sum(a32), u2sum(a33));
        }
        __syncthreads();   // k-reduction join: all partials visible

        // ---- distributed reduce: contiguous float2 per thread -> coalesced STG.64 ----
        {
            float acc0 = 0.f, acc1 = 0.f;
            #pragma unroll
            for (int gg = 0; gg < NG; ++gg) {
                const float* sc = scratch + (size_t)(gg * 64) * SCR;
                acc0 += sc[(size_t)own0 * SCR + slot];
                acc1 += sc[(size_t)own1 * SCR + slot];
            }
            const float xr = g_xT[(size_t)t * BB + row0g + row_l];   // L2-resident, coalesced
            float v0 = tanhf(fmaf(xr, s_wb[c0], s_wb[32 + c0]) + acc0);
            float v1 = tanhf(fmaf(xr, s_wb[c1], s_wb[32 + c1]) + acc1);
            *(float2*)(g_h[p ^ 1] + (size_t)(row0g + row_l) * HH + col0g + c0) =
                make_float2(v0, v1);
        }
        __syncthreads();   // all h_new stores done before release
        if (tid == 0) st_release(&g_flag[blockIdx.x * 32], base + 2 + (unsigned)t);
        p ^= 1;
    }
    // final h in g_h[0] (784 steps, even)

    // ---- Epilogue on block 0: wait whole grid, then head + log-softmax ----
    if (blockIdx.x == 0) {
        if (tid < NBLK)
            spin_until(&g_flag[tid * 32], base + 1 + TT);
        __syncthreads();

        __shared__ float s_loss[BB];
        __shared__ int   s_corr[BB];
        if (tid < BB) {
            const int b = tid;
            const float* hrow = g_h[0] + (size_t)b * HH;

            float logit[NC];
            #pragma unroll
            for (int c = 0; c < NC; ++c) logit[c] = lin_b[c];
            for (int k = 0; k < HH; k += 4) {
                float4 hv = __ldcg((const float4*)(hrow + k));
                #pragma unroll
                for (int c = 0; c < NC; ++c) {
                    float4 wv = *(const float4*)(lin_W + (size_t)c * HH + k);
                    logit[c] = fmaf(hv.x, wv.x, logit[c]);
                    logit[c] = fmaf(hv.y, wv.y, logit[c]);
                    logit[c] = fmaf(hv.z, wv.z, logit[c]);
                    logit[c] = fmaf(hv.w, wv.w, logit[c]);
                }
            }
            float mx = logit[0]; int pred = 0;
            #pragma unroll
            for (int c = 1; c < NC; ++c)
                if (logit[c] > mx) { mx = logit[c]; pred = c; }
            float se = 0.f;
            #pragma unroll
            for (int c = 0; c < NC; ++c) se += expf(logit[c] - mx);
            const float lse = mx + logf(se);

            const int yb = is_i64 ? (int)((const long long*)y_raw)[b]
                                  : ((const int*)y_raw)[b];
            s_loss[b] = lse - logit[yb];
            s_corr[b] = (pred == yb) ? 1 : 0;
        }
        __syncthreads();
        if (tid == 0) {
            float L = 0.f; int C = 0;
            for (int i = 0; i < BB; ++i) { L += s_loss[i]; C += s_corr[i]; }
            out[0] = L / (float)BB;
            if (out_size >= 2) out[1] = (float)C;
        }
    }
}

extern "C" void kernel_launch(void* const* d_in, const int* in_sizes, int n_in,
                              void* d_out, int out_size) {
    // Identify inputs by element count (robust to ordering).
    const float *inputs = 0, *W_ih = 0, *b_ih = 0, *W_hh = 0, *b_hh = 0,
                *lin_W = 0, *lin_b = 0;
    const void *y = 0, *order = 0;
    int n512 = 0;
    for (int i = 0; i < n_in; ++i) {
        const int s = in_sizes[i];
        const void* ptr = d_in[i];
        if      (s == 200704) inputs = (const float*)ptr;
        else if (s == 262144) W_hh   = (const float*)ptr;
        else if (s == 5120)   lin_W  = (const float*)ptr;
        else if (s == 10)     lin_b  = (const float*)ptr;
        else if (s == 784)    order  = ptr;
        else if (s == 256)    y      = ptr;
        else if (s == 512) {
            if      (n512 == 0) W_ih = (const float*)ptr;
            else if (n512 == 1) b_ih = (const float*)ptr;
            else                b_hh = (const float*)ptr;
            ++n512;
        }
    }
    float* out = (float*)d_out;

    // smem: w[32][516] + scratch[8][64][20] + wb[64] + u
    const size_t smem_bytes =
        ((size_t)32 * LDH + (size_t)NG * 64 * SCR + 64) * sizeof(float) + 64;
    cudaFuncSetAttribute(rnn_persistent,
                         cudaFuncAttributeMaxDynamicSharedMemorySize, (int)smem_bytes);
    rnn_persistent<<<NBLK, NTHR, smem_bytes>>>(inputs, y, order, W_ih, b_ih,
                                               W_hh, b_hh, lin_W, lin_b, out,
                                               out_size);
}

// round 16
// speedup vs baseline: 1.4716x; 1.2842x over previous
#include <cuda_runtime.h>
#include <cuda_fp16.h>
#include <math.h>

#define BB 256
#define TT 784
#define HH 512
#define NC 10

#define NBLK 128           // 8 row-groups x 16 col-blocks
#define NTHR 512           // 16 warps = 16 k-slices of 32
#define SPIN_CAP 10000000u

typedef unsigned int u32;

// Device scratch (no allocation). h stored as fp16 hi + fp16 lo (captures fp32 to ~2^-23).
__device__ __align__(16) __half g_hb[2][2][BB * HH];   // [buf][hi/lo][b*H]
__device__ __align__(16) float g_xT[TT * BB];          // inputs[:, order] transposed
__device__ unsigned g_flag[NBLK * 32];                 // monotonic per-CTA flags

__device__ __forceinline__ void st_release(unsigned* p, unsigned v) {
    asm volatile("st.release.gpu.global.u32 [%0], %1;" :: "l"(p), "r"(v) : "memory");
}
__device__ __forceinline__ unsigned ld_acquire(const unsigned* p) {
    unsigned v;
    asm volatile("ld.acquire.gpu.global.u32 %0, [%1];" : "=r"(v) : "l"(p) : "memory");
    return v;
}
__device__ __forceinline__ void spin_until(const unsigned* p, unsigned target) {
    unsigned v, n = 0;
    do { v = ld_acquire(p); } while ((int)(v - target) < 0 && ++n < SPIN_CAP);
}
__device__ __forceinline__ u32 packh(__half a, __half b) {
    __half2 h = __halves2half2(a, b);
    return *(u32*)&h;
}

// m16n8k16 fp16 MMA, fp32 accum (baseline PTX, sm_80+; legacy HMMA pipe on sm_103)
#define MMA(d, A, B)                                                        \
    asm volatile("mma.sync.aligned.m16n8k16.row.col.f32.f16.f16.f32 "      \
                 "{%0,%1,%2,%3}, {%4,%5,%6,%7}, {%8,%9}, {%0,%1,%2,%3};"   \
                 : "+f"((d)[0]), "+f"((d)[1]), "+f"((d)[2]), "+f"((d)[3])  \
                 : "r"((A)[0]), "r"((A)[1]), "r"((A)[2]), "r"((A)[3]),     \
                   "r"((B)[0]), "r"((B)[1]))

extern "C" __global__ void __launch_bounds__(NTHR, 1)
rnn_mma(const float* __restrict__ inputs,
        const void* __restrict__ y_raw,
        const void* __restrict__ order_raw,
        const float* __restrict__ W_ih,
        const float* __restrict__ b_ih,
        const float* __restrict__ W_hh,
        const float* __restrict__ b_hh,
        const float* __restrict__ lin_W,
        const float* __restrict__ lin_b,
        float* __restrict__ out, int out_size)
{
    extern __shared__ float smem[];
    float* scr    = smem;                 // [16][1024] partial sums (64 KB)
    float* s_wb   = smem + 16 * 1024;     // [0..31]=w_ih, [32..63]=bias (local cols)
    unsigned* s_b = (unsigned*)(s_wb + 64);

    const int tid  = threadIdx.x;
    const int g    = tid >> 5;            // warp = k-slice [32g, 32g+32)
    const int lane = tid & 31;
    const int rb   = blockIdx.x >> 4;
    const int cb   = blockIdx.x & 15;
    const int row0g = rb * 32;
    const int col0g = cb * 32;

    const bool is_i64 = (((const int*)order_raw)[1] == 0);

    if (tid == 0) s_b[0] = g_flag[blockIdx.x * 32];

    // ---- B fragments: W hi/lo, loop-invariant in REGISTERS (no smem W) ----
    // m16n8k16 B layout: b0 = B[2t+{0,1}][n], b1 = B[2t+8+{0,1}][n]; n=lane>>2, t=lane&3.
    u32 Bh[8][2], Bl[8][2];               // [nt*2+kt][reg]
    {
        const int cB = col0g + (lane >> 2);
        const int t4 = 2 * (lane & 3);
        #pragma unroll
        for (int nt = 0; nt < 4; ++nt)
        #pragma unroll
        for (int kt = 0; kt < 2; ++kt) {
            const float* wr = W_hh + (size_t)(cB + nt * 8) * HH + 32 * g + kt * 16 + t4;
            float w0 = wr[0], w1 = wr[1], w8 = wr[8], w9 = wr[9];
            __half h0 = __float2half_rn(w0), h1 = __float2half_rn(w1);
            __half h8 = __float2half_rn(w8), h9 = __float2half_rn(w9);
            Bh[nt * 2 + kt][0] = packh(h0, h1);
            Bh[nt * 2 + kt][1] = packh(h8, h9);
            Bl[nt * 2 + kt][0] = packh(__float2half_rn(w0 - __half2float(h0)),
                                       __float2half_rn(w1 - __half2float(h1)));
            Bl[nt * 2 + kt][1] = packh(__float2half_rn(w8 - __half2float(h8)),
                                       __float2half_rn(w9 - __half2float(h9)));
        }
    }
    if (tid < 32) {
        s_wb[tid]      = W_ih[col0g + tid];
        s_wb[32 + tid] = b_ih[col0g + tid] + b_hh[col0g + tid];
    }
    // zero h0 (own tile, buf0, hi+lo)
    for (int i = tid; i < 512; i += NTHR) {
        int r = i >> 4, cp = (i & 15) * 2;
        size_t off = (size_t)(row0g + r) * HH + col0g + cp;
        *(u32*)(&g_hb[0][0][off]) = 0u;
        *(u32*)(&g_hb[0][1][off]) = 0u;
    }
    // one-time x transpose (this CTA's t-slice; guarded by base+1 flag)
    for (int i = tid; i < 49 * 32; i += NTHR) {
        int tt = 49 * cb + (i >> 5), r = i & 31;
        int o = is_i64 ? (int)((const long long*)order_raw)[tt]
                       : ((const int*)order_raw)[tt];
        g_xT[(size_t)tt * BB + row0g + r] = inputs[(size_t)(row0g + r) * TT + o];
    }
    __syncthreads();
    const unsigned base = s_b[0];
    if (tid == 0) st_release(&g_flag[blockIdx.x * 32], base + 1);

    // Reduce mapping: thread owns scratch offsets {2*tid, 2*tid+1}
    // D layout: v0=(r,2t), v1=(r,2t+1), v2=(r+8,2t), v3=(r+8,2t+1); r=lane>>2, t=lane&3.
    const int ooff  = tid * 2;
    const int tileR = ooff >> 7;
    const int rem   = ooff & 127;
    const int ls    = rem >> 2;
    const int vp    = rem & 3;            // 0 or 2
    const int row_l = 16 * (tileR >> 2) + 4 * vp + (ls >> 2);
    const int col_l = 8 * (tileR & 3) + 2 * (ls & 3);

    // A-load lane geometry: a0=A[r][2t..], a1=A[r+8][..], a2=A[r][2t+8..], a3=A[r+8][2t+8..]
    const int arow = lane >> 2;
    const int akb  = 32 * g + 2 * (lane & 3);

    for (int t = 0; t < TT; ++t) {
        const int p = t & 1;
        // wait: exactly ONE producer (col-block g of my row group publishes my k-slice)
        if (lane == 0)
            spin_until(&g_flag[(((unsigned)rb << 4) + g) * 32], base + 1 + (unsigned)t);
        __syncwarp(0xffffffffu);

        // ---- A fragments (h hi/lo) straight from L2, batched for MLP ----
        const __half* Hhi = g_hb[p][0];
        const __half* Hlo = g_hb[p][1];
        u32 Ah[4][4], Al[4][4];           // [mt*2+kt][reg]
        #pragma unroll
        for (int mt = 0; mt < 2; ++mt)
        #pragma unroll
        for (int kt = 0; kt < 2; ++kt) {
            size_t r0 = (size_t)(row0g + 16 * mt + arow) * HH + akb + 16 * kt;
            size_t r8 = r0 + 8 * (size_t)HH;
            const int ix = mt * 2 + kt;
            Ah[ix][0] = __ldcg((const u32*)(Hhi + r0));
            Ah[ix][1] = __ldcg((const u32*)(Hhi + r8));
            Ah[ix][2] = __ldcg((const u32*)(Hhi + r0 + 8));
            Ah[ix][3] = __ldcg((const u32*)(Hhi + r8 + 8));
            Al[ix][0] = __ldcg((const u32*)(Hlo + r0));
            Al[ix][1] = __ldcg((const u32*)(Hlo + r8));
            Al[ix][2] = __ldcg((const u32*)(Hlo + r0 + 8));
            Al[ix][3] = __ldcg((const u32*)(Hlo + r8 + 8));
        }

        float D[2][4][4];
        #pragma unroll
        for (int mt = 0; mt < 2; ++mt)
        #pragma unroll
        for (int nt = 0; nt < 4; ++nt)
        #pragma unroll
        for (int v = 0; v < 4; ++v) D[mt][nt][v] = 0.f;

        // 64 MMA: (hi+lo)x(hi+lo), exact to ~2^-23 per operand
        #pragma unroll
        for (int kt = 0; kt < 2; ++kt)
        #pragma unroll
        for (int mt = 0; mt < 2; ++mt) {
            const int ix = mt * 2 + kt;
            #pragma unroll
            for (int nt = 0; nt < 4; ++nt) {
                const int jx = nt * 2 + kt;
                MMA(D[mt][nt], Ah[ix], Bh[jx]);
                MMA(D[mt][nt], Ah[ix], Bl[jx]);
                MMA(D[mt][nt], Al[ix], Bh[jx]);
                MMA(D[mt][nt], Al[ix], Bl[jx]);
            }
        }

        // publish partials: scr[g][tile*128 + lane*4] (STS.128, conflict-free)
        #pragma unroll
        for (int mt = 0; mt < 2; ++mt)
        #pragma unroll
        for (int nt = 0; nt < 4; ++nt)
            *(float4*)(scr + g * 1024 + (mt * 4 + nt) * 128 + lane * 4) =
                make_float4(D[mt][nt][0], D[mt][nt][1], D[mt][nt][2], D[mt][nt][3]);
        __syncthreads();

        // ---- 16-way k-reduce, 2 outputs per thread (same row, adjacent cols) ----
        {
            float a0 = 0.f, a1 = 0.f;
            #pragma unroll
            for (int gg = 0; gg < 16; ++gg) {
                float2 v = *(const float2*)(scr + gg * 1024 + ooff);
                a0 += v.x; a1 += v.y;
            }
            const float xr = __ldcg(&g_xT[(size_t)t * BB + row0g + row_l]);
            float v0 = tanhf(fmaf(xr, s_wb[col_l],     s_wb[32 + col_l])     + a0);
            float v1 = tanhf(fmaf(xr, s_wb[col_l + 1], s_wb[32 + col_l + 1]) + a1);
            __half h0 = __float2half_rn(v0);
            __half h1 = __float2half_rn(v1);
            __half L0 = __float2half_rn(v0 - __half2float(h0));
            __half L1 = __float2half_rn(v1 - __half2float(h1));
            size_t doff = (size_t)(row0g + row_l) * HH + col0g + col_l;
            *(u32*)(&g_hb[p ^ 1][0][doff]) = packh(h0, h1);
            *(u32*)(&g_hb[p ^ 1][1][doff]) = packh(L0, L1);
        }
        __syncthreads();
        if (tid == 0) st_release(&g_flag[blockIdx.x * 32], base + 2 + (unsigned)t);
    }
    // final h in buf 0 (TT even)

    // ---- Epilogue on block 0: head + log-softmax + loss + correct ----
    if (blockIdx.x == 0) {
        if (tid < NBLK)
            spin_until(&g_flag[tid * 32], base + 1 + TT);
        __syncthreads();

        float* s_loss = scr;                    // scratch is dead now
        int*   s_corr = (int*)(scr + BB);
        if (tid < BB) {
            const __half* hhi = g_hb[0][0] + (size_t)tid * HH;
            const __half* hlo = g_hb[0][1] + (size_t)tid * HH;
            float logit[NC];
            #pragma unroll
            for (int c = 0; c < NC; ++c) logit[c] = lin_b[c];
            for (int k = 0; k < HH; k += 4) {
                uint2 vh = __ldcg((const uint2*)(hhi + k));
                uint2 vl = __ldcg((const uint2*)(hlo + k));
                __half2 a0 = *(__half2*)&vh.x, a1 = *(__half2*)&vh.y;
                __half2 b0 = *(__half2*)&vl.x, b1 = *(__half2*)&vl.y;
                float2 f0 = __half22float2(a0), f1 = __half22float2(a1);
                float2 e0 = __half22float2(b0), e1 = __half22float2(b1);
                float x0 = f0.x + e0.x, x1 = f0.y + e0.y;
                float x2 = f1.x + e1.x, x3 = f1.y + e1.y;
                #pragma unroll
                for (int c = 0; c < NC; ++c) {
                    float4 wv = *(const float4*)(lin_W + (size_t)c * HH + k);
                    logit[c] = fmaf(x0, wv.x, logit[c]);
                    logit[c] = fmaf(x1, wv.y, logit[c]);
                    logit[c] = fmaf(x2, wv.z, logit[c]);
                    logit[c] = fmaf(x3, wv.w, logit[c]);
                }
            }
            float mx = logit[0]; int pred = 0;
            #pragma unroll
            for (int c = 1; c < NC; ++c)
                if (logit[c] > mx) { mx = logit[c]; pred = c; }
            float se = 0.f;
            #pragma unroll
            for (int c = 0; c < NC; ++c) se += expf(logit[c] - mx);
            const float lse = mx + logf(se);
            const int yb = is_i64 ? (int)((const long long*)y_raw)[tid]
                                  : ((const int*)y_raw)[tid];
            s_loss[tid] = lse - logit[yb];
            s_corr[tid] = (pred == yb) ? 1 : 0;
        }
        __syncthreads();
        if (tid == 0) {
            float L = 0.f; int C = 0;
            for (int i = 0; i < BB; ++i) { L += s_loss[i]; C += s_corr[i]; }
            out[0] = L / (float)BB;
            if (out_size >= 2) out[1] = (float)C;
        }
    }
}

extern "C" void kernel_launch(void* const* d_in, const int* in_sizes, int n_in,
                              void* d_out, int out_size) {
    const float *inputs = 0, *W_ih = 0, *b_ih = 0, *W_hh = 0, *b_hh = 0,
                *lin_W = 0, *lin_b = 0;
    const void *y = 0, *order = 0;
    int n512 = 0;
    for (int i = 0; i < n_in; ++i) {
        const int s = in_sizes[i];
        const void* ptr = d_in[i];
        if      (s == 200704) inputs = (const float*)ptr;
        else if (s == 262144) W_hh   = (const float*)ptr;
        else if (s == 5120)   lin_W  = (const float*)ptr;
        else if (s == 10)     lin_b  = (const float*)ptr;
        else if (s == 784)    order  = ptr;
        else if (s == 256)    y      = ptr;
        else if (s == 512) {
            if      (n512 == 0) W_ih = (const float*)ptr;
            else if (n512 == 1) b_ih = (const float*)ptr;
            else                b_hh = (const float*)ptr;
            ++n512;
        }
    }
    float* out = (float*)d_out;

    const size_t smem_bytes = (size_t)16 * 1024 * sizeof(float) + 64 * sizeof(float) + 64;
    cudaFuncSetAttribute(rnn_mma,
                         cudaFuncAttributeMaxDynamicSharedMemorySize, (int)smem_bytes);
    rnn_mma<<<NBLK, NTHR, smem_bytes>>>(inputs, y, order, W_ih, b_ih,
                                        W_hh, b_hh, lin_W, lin_b, out, out_size);
}

// round 17
// speedup vs baseline: 2.4272x; 1.6493x over previous
#include <cuda_runtime.h>
#include <cuda_fp16.h>
#include <math.h>

#define BB 256
#define TT 784
#define HH 512
#define NC 10

#define NBLK 128           // 8 row-groups x 16 col-blocks
#define NTHR 512           // 16 warps = 16 k-slices of 32
#define SPIN_CAP 10000000u

typedef unsigned int u32;

// Device scratch (no allocation).
// h stored in MMA A-FRAGMENT order: region per (CTA, hi/lo, buf) of 512 u32,
// slot = (mtkt*32 + lane)*4 + reg  ->  h[16*mt + 8*(reg&1) + (lane>>2)]
//                                       [16*kt + 8*(reg>>1) + 2*(lane&3) .. +1]
__device__ __align__(16) u32 g_hf[2][2][NBLK][512];   // [buf][hi/lo][region][slot]
__device__ __align__(16) float g_hfinal[BB * HH];     // fp32 final h for the head
__device__ __align__(16) float g_xT[TT * BB];         // inputs[:, order] transposed
__device__ unsigned g_flag[NBLK * 32];                // monotonic per-CTA flags

__device__ __forceinline__ void st_release(unsigned* p, unsigned v) {
    asm volatile("st.release.gpu.global.u32 [%0], %1;" :: "l"(p), "r"(v) : "memory");
}
__device__ __forceinline__ unsigned ld_acquire(const unsigned* p) {
    unsigned v;
    asm volatile("ld.acquire.gpu.global.u32 %0, [%1];" : "=r"(v) : "l"(p) : "memory");
    return v;
}
__device__ __forceinline__ void spin_until(const unsigned* p, unsigned target) {
    unsigned v, n = 0;
    do { v = ld_acquire(p); } while ((int)(v - target) < 0 && ++n < SPIN_CAP);
}
__device__ __forceinline__ u32 packh(__half a, __half b) {
    __half2 h = __halves2half2(a, b);
    return *(u32*)&h;
}

// m16n8k16 fp16 MMA, fp32 accum (baseline PTX, sm_80+)
#define MMA(d, A, B)                                                        \
    asm volatile("mma.sync.aligned.m16n8k16.row.col.f32.f16.f16.f32 "      \
                 "{%0,%1,%2,%3}, {%4,%5,%6,%7}, {%8,%9}, {%0,%1,%2,%3};"   \
                 : "+f"((d)[0]), "+f"((d)[1]), "+f"((d)[2]), "+f"((d)[3])  \
                 : "r"((A)[0]), "r"((A)[1]), "r"((A)[2]), "r"((A)[3]),     \
                   "r"((B)[0]), "r"((B)[1]))

extern "C" __global__ void __launch_bounds__(NTHR, 1)
rnn_mma(const float* __restrict__ inputs,
        const void* __restrict__ y_raw,
        const void* __restrict__ order_raw,
        const float* __restrict__ W_ih,
        const float* __restrict__ b_ih,
        const float* __restrict__ W_hh,
        const float* __restrict__ b_hh,
        const float* __restrict__ lin_W,
        const float* __restrict__ lin_b,
        float* __restrict__ out, int out_size)
{
    extern __shared__ float smem[];
    float* scr    = smem;                 // [16][1024] partial sums (64 KB)
    float* s_wb   = smem + 16 * 1024;     // [0..31]=w_ih, [32..63]=bias (local cols)
    unsigned* s_b = (unsigned*)(s_wb + 64);

    const int tid  = threadIdx.x;
    const int g    = tid >> 5;            // warp = k-slice [32g, 32g+32)
    const int lane = tid & 31;
    const int bx   = blockIdx.x;
    const int rb   = bx >> 4;
    const int cb   = bx & 15;
    const int row0g = rb * 32;
    const int col0g = cb * 32;

    const bool is_i64 = (((const int*)order_raw)[1] == 0);

    if (tid == 0) s_b[0] = g_flag[bx * 32];

    // ---- B fragments: W hi/lo, loop-invariant in REGISTERS ----
    u32 Bh[8][2], Bl[8][2];               // [nt*2+kt][reg]
    {
        const int cB = col0g + (lane >> 2);
        const int t4 = 2 * (lane & 3);
        #pragma unroll
        for (int nt = 0; nt < 4; ++nt)
        #pragma unroll
        for (int kt = 0; kt < 2; ++kt) {
            const float* wr = W_hh + (size_t)(cB + nt * 8) * HH + 32 * g + kt * 16 + t4;
            float w0 = wr[0], w1 = wr[1], w8 = wr[8], w9 = wr[9];
            __half h0 = __float2half_rn(w0), h1 = __float2half_rn(w1);
            __half h8 = __float2half_rn(w8), h9 = __float2half_rn(w9);
            Bh[nt * 2 + kt][0] = packh(h0, h1);
            Bh[nt * 2 + kt][1] = packh(h8, h9);
            Bl[nt * 2 + kt][0] = packh(__float2half_rn(w0 - __half2float(h0)),
                                       __float2half_rn(w1 - __half2float(h1)));
            Bl[nt * 2 + kt][1] = packh(__float2half_rn(w8 - __half2float(h8)),
                                       __float2half_rn(w9 - __half2float(h9)));
        }
    }
    if (tid < 32) {
        s_wb[tid]      = W_ih[col0g + tid];
        s_wb[32 + tid] = b_ih[col0g + tid] + b_hh[col0g + tid];
    }
    // zero h0: this CTA's fragment regions in buf 0 (hi+lo)
    g_hf[0][0][bx][tid] = 0u;
    g_hf[0][1][bx][tid] = 0u;
    // one-time x transpose (this CTA's t-slice; guarded by base+1 flag)
    for (int i = tid; i < 49 * 32; i += NTHR) {
        int tt = 49 * cb + (i >> 5), r = i & 31;
        int o = is_i64 ? (int)((const long long*)order_raw)[tt]
                       : ((const int*)order_raw)[tt];
        g_xT[(size_t)tt * BB + row0g + r] = inputs[(size_t)(row0g + r) * TT + o];
    }
    __syncthreads();
    const unsigned base = s_b[0];
    if (tid == 0) st_release(&g_flag[bx * 32], base + 1);

    // ---- Reduce-phase mapping: thread tid owns fragment slot tid (coalesced STG) ----
    const int f_reg  = tid & 3;
    const int f_lane = (tid >> 2) & 31;
    const int f_mtkt = tid >> 7;
    const int row_l  = 16 * (f_mtkt >> 1) + 8 * (f_reg & 1) + (f_lane >> 2);
    const int col_l  = 16 * (f_mtkt & 1)  + 8 * (f_reg >> 1) + 2 * (f_lane & 3);
    // scratch offset of (row_l, col pair) under the D-publish layout (validated in R16)
    const int soff = ((row_l >> 4) * 4 + (col_l >> 3)) * 128
                   + (row_l & 7) * 16 + ((col_l & 7) >> 1) * 4 + ((row_l >> 3) & 1) * 2;

    for (int t = 0; t < TT; ++t) {
        const int p = t & 1;
        // prefetch x (static data, independent of h)
        const float xr = __ldcg(&g_xT[(size_t)t * BB + row0g + row_l]);

        // wait: exactly ONE producer (col-block g of my row group owns my k-slice)
        if (lane == 0)
            spin_until(&g_flag[(((unsigned)rb << 4) + g) * 32], base + 1 + (unsigned)t);
        __syncwarp(0xffffffffu);

        // ---- A fragments straight from L2 in fragment order: 8x LDG.128 ----
        const u32* Rh = &g_hf[p][0][(rb << 4) + g][0];
        const u32* Rl = &g_hf[p][1][(rb << 4) + g][0];
        u32 Ah[4][4], Al[4][4];
        #pragma unroll
        for (int ix = 0; ix < 4; ++ix) {
            uint4 vh = __ldcg((const uint4*)Rh + ix * 32 + lane);
            uint4 vl = __ldcg((const uint4*)Rl + ix * 32 + lane);
            Ah[ix][0] = vh.x; Ah[ix][1] = vh.y; Ah[ix][2] = vh.z; Ah[ix][3] = vh.w;
            Al[ix][0] = vl.x; Al[ix][1] = vl.y; Al[ix][2] = vl.z; Al[ix][3] = vl.w;
        }

        float D[2][4][4];
        #pragma unroll
        for (int mt = 0; mt < 2; ++mt)
        #pragma unroll
        for (int nt = 0; nt < 4; ++nt)
        #pragma unroll
        for (int v = 0; v < 4; ++v) D[mt][nt][v] = 0.f;

        // 48 MMA: hi*hi + hi*lo + lo*hi  (lo*lo ~2^-24 relative, dropped)
        #pragma unroll
        for (int kt = 0; kt < 2; ++kt)
        #pragma unroll
        for (int mt = 0; mt < 2; ++mt) {
            const int ix = mt * 2 + kt;
            #pragma unroll
            for (int nt = 0; nt < 4; ++nt) {
                const int jx = nt * 2 + kt;
                MMA(D[mt][nt], Ah[ix], Bh[jx]);
                MMA(D[mt][nt], Ah[ix], Bl[jx]);
                MMA(D[mt][nt], Al[ix], Bh[jx]);
            }
        }

        // publish partials: scr[g][tile*128 + lane*4] (STS.128, conflict-free)
        #pragma unroll
        for (int mt = 0; mt < 2; ++mt)
        #pragma unroll
        for (int nt = 0; nt < 4; ++nt)
            *(float4*)(scr + g * 1024 + (mt * 4 + nt) * 128 + lane * 4) =
                make_float4(D[mt][nt][0], D[mt][nt][1], D[mt][nt][2], D[mt][nt][3]);
        __syncthreads();

        // ---- 16-way k-reduce; outputs written in FRAGMENT order (coalesced) ----
        {
            float a0 = 0.f, a1 = 0.f;
            #pragma unroll
            for (int gg = 0; gg < 16; ++gg) {
                float2 v = *(const float2*)(scr + gg * 1024 + soff);
                a0 += v.x; a1 += v.y;
            }
            float v0 = tanhf(fmaf(xr, s_wb[col_l],     s_wb[32 + col_l])     + a0);
            float v1 = tanhf(fmaf(xr, s_wb[col_l + 1], s_wb[32 + col_l + 1]) + a1);
            __half h0 = __float2half_rn(v0);
            __half h1 = __float2half_rn(v1);
            __half L0 = __float2half_rn(v0 - __half2float(h0));
            __half L1 = __float2half_rn(v1 - __half2float(h1));
            const int pn = p ^ 1;
            g_hf[pn][0][bx][tid] = packh(h0, h1);   // STG.32, fully coalesced
            g_hf[pn][1][bx][tid] = packh(L0, L1);
            if (t == TT - 1) {                      // fp32 h for the head
                float* hf = g_hfinal + (size_t)(row0g + row_l) * HH + col0g + col_l;
                hf[0] = v0; hf[1] = v1;
            }
        }
        __syncthreads();
        if (tid == 0) st_release(&g_flag[bx * 32], base + 2 + (unsigned)t);
    }

    // ---- Epilogue on block 0: head + log-softmax + loss + correct ----
    if (blockIdx.x == 0) {
        if (tid < NBLK)
            spin_until(&g_flag[tid * 32], base + 1 + TT);
        __syncthreads();

        float* s_loss = scr;                    // scratch is dead now
        int*   s_corr = (int*)(scr + BB);
        if (tid < BB) {
            const float* hrow = g_hfinal + (size_t)tid * HH;
            float logit[NC];
            #pragma unroll
            for (int c = 0; c < NC; ++c) logit[c] = lin_b[c];
            for (int k = 0; k < HH; k += 4) {
                float4 hv = __ldcg((const float4*)(hrow + k));
                #pragma unroll
                for (int c = 0; c < NC; ++c) {
                    float4 wv = *(const float4*)(lin_W + (size_t)c * HH + k);
                    logit[c] = fmaf(hv.x, wv.x, logit[c]);
                    logit[c] = fmaf(hv.y, wv.y, logit[c]);
                    logit[c] = fmaf(hv.z, wv.z, logit[c]);
                    logit[c] = fmaf(hv.w, wv.w, logit[c]);
                }
            }
            float mx = logit[0]; int pred = 0;
            #pragma unroll
            for (int c = 1; c < NC; ++c)
                if (logit[c] > mx) { mx = logit[c]; pred = c; }
            float se = 0.f;
            #pragma unroll
            for (int c = 0; c < NC; ++c) se += expf(logit[c] - mx);
            const float lse = mx + logf(se);
            const int yb = is_i64 ? (int)((const long long*)y_raw)[tid]
                                  : ((const int*)y_raw)[tid];
            s_loss[tid] = lse - logit[yb];
            s_corr[tid] = (pred == yb) ? 1 : 0;
        }
        __syncthreads();
        if (tid == 0) {
            float L = 0.f; int C = 0;
            for (int i = 0; i < BB; ++i) { L += s_loss[i]; C += s_corr[i]; }
            out[0] = L / (float)BB;
            if (out_size >= 2) out[1] = (float)C;
        }
    }
}

extern "C" void kernel_launch(void* const* d_in, const int* in_sizes, int n_in,
                              void* d_out, int out_size) {
    const float *inputs = 0, *W_ih = 0, *b_ih = 0, *W_hh = 0, *b_hh = 0,
                *lin_W = 0, *lin_b = 0;
    const void *y = 0, *order = 0;
    int n512 = 0;
    for (int i = 0; i < n_in; ++i) {
        const int s = in_sizes[i];
        const void* ptr = d_in[i];
        if      (s == 200704) inputs = (const float*)ptr;
        else if (s == 262144) W_hh   = (const float*)ptr;
        else if (s == 5120)   lin_W  = (const float*)ptr;
        else if (s == 10)     lin_b  = (const float*)ptr;
        else if (s == 784)    order  = ptr;
        else if (s == 256)    y      = ptr;
        else if (s == 512) {
            if      (n512 == 0) W_ih = (const float*)ptr;
            else if (n512 == 1) b_ih = (const float*)ptr;
            else                b_hh = (const float*)ptr;
            ++n512;
        }
    }
    float* out = (float*)d_out;

    const size_t smem_bytes = (size_t)16 * 1024 * sizeof(float) + 64 * sizeof(float) + 64;
    cudaFuncSetAttribute(rnn_mma,
                         cudaFuncAttributeMaxDynamicSharedMemorySize, (int)smem_bytes);
    rnn_mma<<<NBLK, NTHR, smem_bytes>>>(inputs, y, order, W_ih, b_ih,
                                        W_hh, b_hh, lin_W, lin_b, out, out_size);
}